// round 12
// baseline (speedup 1.0000x reference)
#include <cuda_runtime.h>
#include <cuda_bf16.h>

// S4D live path == causal conv of u with K[h,m] = sum_n c[h,n] * r[h,n]^m,
// i.e. a bank of first-order IIR filters. Single fused kernel:
//  - each CTA owns one (b,h) row of L=4096
//  - warp 0 computes per-mode (dtA, c); thread 0 merges bitwise-identical
//    poles (for this data: 32 modes -> 1 pole), list broadcast via smem
//  - per-thread contiguous SEG=8 elements loaded directly as 2x float4
//    (no smem staging), blocked Kogge-Stone scan of affine carry maps
//    (x -> R*x + s) across 512 threads, direct float4 stores.

#define LROW 4096
#define TPB  512
#define SEG  8              // LROW / TPB
#define NW   (TPB / 32)

__global__ __launch_bounds__(TPB, 3)
void s4d_fused_kernel(const float* __restrict__ u,
                      const float* __restrict__ C,
                      const float* __restrict__ log_dt,
                      const float* __restrict__ log_A_real,
                      float* __restrict__ y, int H, int NH) {
    __shared__ float sA[32], sC[32];      // raw per-mode dtA, c
    __shared__ float sPA[32], sPC[32];    // merged compact poles
    __shared__ int   sCnt;
    __shared__ float warpT[NW];

    const int bh   = blockIdx.x;
    const int h    = bh % H;
    const int tid  = threadIdx.x;
    const int lane = tid & 31;
    const int warp = tid >> 5;

    // Issue the row loads first so they are in flight during pole setup.
    const float4* __restrict__ u4 = (const float4*)(u + (size_t)bh * LROW);
    const float4 a0 = u4[tid * 2 + 0];
    const float4 a1 = u4[tid * 2 + 1];

    // --- per-head pole computation (warp 0 lanes), then merge by thread 0 ---
    const int nh = (NH < 32) ? NH : 32;
    if (tid < nh) {
        float dt  = expf(log_dt[h]);
        float A   = -expf(log_A_real[h * NH + tid]);
        float dtA = A * dt;
        sA[tid] = dtA;
        sC[tid] = C[(h * NH + tid) * 2] * (expf(dtA) - 1.0f) / A;
    }
    __syncthreads();
    if (tid == 0) {
        int cnt = 0;
        for (int n = 0; n < nh; n++) {
            float a = sA[n], c = sC[n];
            int f = -1;
            for (int k = 0; k < cnt; k++)
                if (__float_as_int(sPA[k]) == __float_as_int(a)) { f = k; break; }
            if (f >= 0) sPC[f] += c;
            else { sPA[cnt] = a; sPC[cnt] = c; cnt++; }
        }
        sCnt = cnt;
    }
    __syncthreads();

    float ur[SEG] = {a0.x, a0.y, a0.z, a0.w, a1.x, a1.y, a1.z, a1.w};
    float yr[SEG];
#pragma unroll
    for (int i = 0; i < SEG; i++) yr[i] = 0.0f;

    const int cnt = sCnt;
    for (int p = 0; p < cnt; p++) {
        const float dtA = sPA[p];
        const float c   = sPC[p];
        const float r   = expf(dtA);

        // Pass 1: local recurrence from state 0
        float s = 0.0f;
#pragma unroll
        for (int i = 0; i < SEG; i++) s = fmaf(r, s, ur[i]);

        // Rseg = r^SEG via squarings
        float Rseg = r;
#pragma unroll
        for (int q = 0; q < 3; q++) Rseg *= Rseg;   // r^8 (SEG=8)

        // Inclusive warp scan of carries under combine (x -> Rseg*x + s)
        float v = s, pw = Rseg;
#pragma unroll
        for (int k = 1; k < 32; k <<= 1) {
            float t = __shfl_up_sync(0xffffffffu, v, k);
            if (lane >= k) v = fmaf(pw, t, v);
            pw *= pw;
        }
        // After 5 squarings, pw == Rseg^32 == per-warp decay Rwarp.
        const float Rwarp = pw;

        if (lane == 31) warpT[warp] = v;
        __syncthreads();

        // Cross-warp prefix (serial, <= NW-1 FMAs on broadcast LDS)
        float J = 0.0f;
        for (int w = 0; w < warp; w++) J = fmaf(J, Rwarp, warpT[w]);
        __syncthreads();                 // warpT reused next pole

        // Exclusive carry for this thread's segment
        float E = __shfl_up_sync(0xffffffffu, v, 1);
        if (lane == 0) E = 0.0f;
        float carry = fmaf(J, expf(dtA * (float)(SEG * lane)), E);

        // Pass 2: replay with carry, accumulate output
        s = carry;
#pragma unroll
        for (int i = 0; i < SEG; i++) {
            s     = fmaf(r, s, ur[i]);
            yr[i] = fmaf(c, s, yr[i]);
        }
    }

    float4* __restrict__ y4 = (float4*)(y + (size_t)bh * LROW);
    y4[tid * 2 + 0] = make_float4(yr[0], yr[1], yr[2], yr[3]);
    y4[tid * 2 + 1] = make_float4(yr[4], yr[5], yr[6], yr[7]);
}

// ---------------------------------------------------------------------------
extern "C" void kernel_launch(void* const* d_in, const int* in_sizes, int n_in,
                              void* d_out, int out_size) {
    const float* u          = (const float*)d_in[0];   // (B,H,L)
    const float* C          = (const float*)d_in[1];   // (H,N/2,2)
    const float* log_dt     = (const float*)d_in[2];   // (H,)
    const float* log_A_real = (const float*)d_in[3];   // (H,N/2)
    float*       y          = (float*)d_out;

    const int H    = in_sizes[2];
    const int NH   = in_sizes[3] / H;
    const int rows = in_sizes[0] / LROW;               // B*H

    s4d_fused_kernel<<<rows, TPB>>>(u, C, log_dt, log_A_real, y, H, NH);
}

// round 14
// speedup vs baseline: 2.2081x; 2.2081x over previous
#include <cuda_runtime.h>
#include <cuda_bf16.h>

// S4D live path == bank of first-order IIR filters:
//   s_n[l] = u[l] + r_n*s_n[l-1],  y[l] = sum_n c_n*s_n[l],
//   r_n = exp(dtA[h,n]),  c_n = C_real*(exp(dtA)-1)/A.
// Fully fused single kernel, one CTA per (b,h) row:
//   - warp 0 computes per-mode poles in parallel and merges bitwise-identical
//     ones with a convergent shuffle-compare (this data: 32 modes -> 1 pole),
//     overlapped with the smem staging done by all warps
//   - blocked Kogge-Stone scan of affine carry maps (x -> R*x + s)
//   - both passes read u from padded smem (no big register arrays ->
//     high occupancy); cnt==1 fast path writes y in place over the u buffer

#define LROW 4096
#define TPB  256
#define SEG  16                 // LROW / TPB
#define NW   (TPB / 32)
#define PAD(l) ((l) + ((l) >> 4))   // stride-17 padding, conflict-free

__global__ __launch_bounds__(TPB, 5)
void s4d_fused(const float* __restrict__ u,
               const float* __restrict__ C,
               const float* __restrict__ log_dt,
               const float* __restrict__ log_A_real,
               float* __restrict__ y, int H, int NH)
{
    __shared__ float sbuf[LROW + LROW / 16];   // staged u (padded)
    __shared__ float ybuf[LROW + LROW / 16];   // y accumulator (cnt>1 path)
    __shared__ float sPA[32], sPC[32];         // compact poles
    __shared__ int   sCnt;
    __shared__ float warpT[NW];

    const int bh   = blockIdx.x;
    const int h    = bh % H;
    const int tid  = threadIdx.x;
    const int lane = tid & 31;
    const int warp = tid >> 5;

    const float* __restrict__ urow = u + (size_t)bh * LROW;
    float* __restrict__       yrow = y + (size_t)bh * LROW;

    // ---- warp 0: issue tiny pole loads FIRST so latency overlaps staging ----
    const int nh = (NH < 32) ? NH : 32;
    float m_ldt = 0.f, m_lA = 0.f, m_C = 0.f;
    if (warp == 0 && lane < nh) {
        m_ldt = log_dt[h];
        m_lA  = log_A_real[h * NH + lane];
        m_C   = C[(h * NH + lane) * 2];
    }

    // ---- all warps: coalesced stage u -> padded smem ----
#pragma unroll
    for (int k = 0; k < LROW / TPB; k++) {
        int l = k * TPB + tid;
        sbuf[PAD(l)] = urow[l];
    }

    // ---- warp 0: compute poles, merge duplicates (convergent, no serial t0) ----
    if (warp == 0) {
        float dtA, c;
        unsigned mybits;
        if (lane < nh) {
            float dt = expf(m_ldt);
            float A  = -expf(m_lA);
            dtA = A * dt;
            c   = m_C * (expf(dtA) - 1.0f) / A;
            mybits = __float_as_uint(dtA);
        } else {
            dtA = 0.f; c = 0.f;
            mybits = 0xFF800001u ^ (unsigned)lane;   // unique sentinel per lane
        }
        float csum  = 0.f;
        int   firstj = 32;
#pragma unroll
        for (int j = 0; j < 32; j++) {
            unsigned bj = __shfl_sync(0xffffffffu, mybits, j);
            float    cj = __shfl_sync(0xffffffffu, c, j);
            if (j < nh && bj == mybits) {
                csum += cj;
                if (j < firstj) firstj = j;
            }
        }
        bool leader = (lane < nh) && (firstj == lane);
        unsigned lb = __ballot_sync(0xffffffffu, leader);
        if (leader) {
            int idx = __popc(lb & ((1u << lane) - 1u));
            sPA[idx] = dtA;
            sPC[idx] = csum;
        }
        if (lane == 0) sCnt = __popc(lb);
    }
    __syncthreads();   // publishes poles AND staged u

    const int   cnt  = sCnt;
    float*      obuf = (cnt == 1) ? sbuf : ybuf;   // in-place when single pole
    const int   base = tid * (SEG + 1);

    for (int p = 0; p < cnt; p++) {
        const float dtA = sPA[p];
        const float cc  = sPC[p];
        const float r   = expf(dtA);

        // Pass 1: local recurrence from state 0 (u read from smem)
        float s = 0.f;
#pragma unroll
        for (int i = 0; i < SEG; i++) s = fmaf(r, s, sbuf[base + i]);

        // Rseg = r^SEG via squarings (SEG=16 -> 4 squarings)
        float Rseg = r;
#pragma unroll
        for (int q = 0; q < 4; q++) Rseg *= Rseg;

        // Inclusive warp scan of carries under combine (x -> Rseg*x + s)
        float v = s, pw = Rseg;
#pragma unroll
        for (int k = 1; k < 32; k <<= 1) {
            float t = __shfl_up_sync(0xffffffffu, v, k);
            if (lane >= k) v = fmaf(pw, t, v);
            pw *= pw;
        }
        const float Rwarp = pw;                 // Rseg^32 after 5 squarings
        if (lane == 31) warpT[warp] = v;
        __syncthreads();

        // Cross-warp prefix (<= NW-1 FMAs on broadcast LDS)
        float J = 0.f;
        for (int w = 0; w < warp; w++) J = fmaf(J, Rwarp, warpT[w]);

        // Exclusive carry for this thread's segment
        float E = __shfl_up_sync(0xffffffffu, v, 1);
        if (lane == 0) E = 0.f;
        float carry = fmaf(J, expf(dtA * (float)(SEG * lane)), E);

        // Pass 2: replay with carry, emit/accumulate y in smem
        s = carry;
        if (p == 0) {
#pragma unroll
            for (int i = 0; i < SEG; i++) {
                s = fmaf(r, s, sbuf[base + i]);
                obuf[base + i] = cc * s;        // cnt==1: overwrites sbuf slot just read
            }
        } else {
#pragma unroll
            for (int i = 0; i < SEG; i++) {
                s = fmaf(r, s, sbuf[base + i]);
                obuf[base + i] += cc * s;
            }
        }
        if (p + 1 < cnt) __syncthreads();       // warpT reused next pole
    }
    __syncthreads();

    // Coalesced store from padded smem
#pragma unroll
    for (int k = 0; k < LROW / TPB; k++) {
        int l = k * TPB + tid;
        yrow[l] = obuf[PAD(l)];
    }
}

// ---------------------------------------------------------------------------
extern "C" void kernel_launch(void* const* d_in, const int* in_sizes, int n_in,
                              void* d_out, int out_size) {
    const float* u          = (const float*)d_in[0];   // (B,H,L)
    const float* C          = (const float*)d_in[1];   // (H,N/2,2)
    const float* log_dt     = (const float*)d_in[2];   // (H,)
    const float* log_A_real = (const float*)d_in[3];   // (H,N/2)
    float*       y          = (float*)d_out;

    const int H    = in_sizes[2];
    const int NH   = in_sizes[3] / H;
    const int rows = in_sizes[0] / LROW;               // B*H

    s4d_fused<<<rows, TPB>>>(u, C, log_dt, log_A_real, y, H, NH);
}

// round 16
// speedup vs baseline: 2.7216x; 1.2325x over previous
#include <cuda_runtime.h>
#include <cuda_bf16.h>

// S4D live path == bank of first-order IIR filters:
//   s_n[l] = u[l] + r_n*s_n[l-1],  y[l] = sum_n c_n*s_n[l].
// Fully fused, ZERO-smem data path. One CTA per (b,h) row (L=4096):
//   - warp w owns chunk [w*512, (w+1)*512), processed as 4 serial groups of
//     128 elements, element-per-lane (lane holds 4 consecutive floats via
//     one coalesced LDG.128)
//   - intra-group: 3 intra-lane FMAs + uniform-multiplier Kogge-Stone
//     shuffle scan of affine carry maps (x -> R*x + t)
//   - cross-warp carries through an 8-float smem handoff (warpT)
//   - pass 1 computes chunk totals (DRAM read), pass 2 replays re-reading
//     the same 2KB/warp from L1 and stores y with coalesced STG.128
//   - warp 0 computes per-mode poles and merges bitwise-identical ones with
//     a convergent shuffle-compare (this data: 32 modes -> 1 pole)

#define LROW 4096
#define TPB  256
#define NW   (TPB / 32)
#define CH4  (LROW / 4 / NW)     // float4s per warp chunk = 128 (512 floats)

template<bool PREF, bool ACC>
__device__ __forceinline__
void do_pole(float dtA, float c,
             const float4* __restrict__ u4, float4* __restrict__ y4,
             int cbase, int lane, int warp, float* warpT,
             float4 f0, float4 f1, float4 f2, float4 f3)
{
    const float r = expf(dtA);
    float R4 = r * r; R4 *= R4;                          // r^4
    const float Rlane = expf(dtA * (float)(4 * lane));   // r^(4*lane)

    // ---- pass 1: chunk-total additive carry (scan totals only) ----
    float S = 0.f;
    float Rgrp = 1.f;
#pragma unroll
    for (int g = 0; g < 4; g++) {
        float4 a;
        if (PREF) a = (g == 0) ? f0 : (g == 1) ? f1 : (g == 2) ? f2 : f3;
        else      a = u4[cbase + g * 32];
        // lane-local affine additive term over its 4 elements
        float t = fmaf(r, fmaf(r, fmaf(r, a.x, a.y), a.z), a.w);
        // warp scan of affine carries (uniform multiplier R4)
        float v = t, pw = R4;
#pragma unroll
        for (int k = 1; k < 32; k <<= 1) {
            float tt = __shfl_up_sync(0xffffffffu, v, k);
            if (lane >= k) v = fmaf(pw, tt, v);
            pw *= pw;
        }
        float T = __shfl_sync(0xffffffffu, v, 31);  // group total
        S = fmaf(pw, S, T);                         // pw == r^128
        Rgrp = pw;
    }
    if (lane == 0) warpT[warp] = S;
    float Rchunk = Rgrp * Rgrp; Rchunk *= Rchunk;    // r^512
    __syncthreads();

    // incoming state for this warp's chunk (broadcast LDS, <= NW-1 FMAs)
    float J = 0.f;
    for (int w = 0; w < warp; w++) J = fmaf(J, Rchunk, warpT[w]);

    // ---- pass 2: replay with carry, emit y ----
    float S0 = J;
#pragma unroll
    for (int g = 0; g < 4; g++) {
        float4 a = u4[cbase + g * 32];               // L1 hit (just read)
        float t = fmaf(r, fmaf(r, fmaf(r, a.x, a.y), a.z), a.w);
        float v = t, pw = R4;
#pragma unroll
        for (int k = 1; k < 32; k <<= 1) {
            float tt = __shfl_up_sync(0xffffffffu, v, k);
            if (lane >= k) v = fmaf(pw, tt, v);
            pw *= pw;
        }
        float e = __shfl_up_sync(0xffffffffu, v, 1);
        if (lane == 0) e = 0.f;
        float st = fmaf(Rlane, S0, e);               // state entering lane
        float s0 = fmaf(r, st, a.x);
        float s1 = fmaf(r, s0, a.y);
        float s2 = fmaf(r, s1, a.z);
        float s3 = fmaf(r, s2, a.w);
        float4 o = make_float4(c * s0, c * s1, c * s2, c * s3);
        if (ACC) {
            float4 prev = y4[cbase + g * 32];
            o.x += prev.x; o.y += prev.y; o.z += prev.z; o.w += prev.w;
        }
        y4[cbase + g * 32] = o;
        float T = __shfl_sync(0xffffffffu, v, 31);
        S0 = fmaf(pw, S0, T);                        // pw == r^128
    }
}

__global__ __launch_bounds__(TPB, 6)
void s4d_fused(const float* __restrict__ u,
               const float* __restrict__ C,
               const float* __restrict__ log_dt,
               const float* __restrict__ log_A_real,
               float* __restrict__ y, int H, int NH)
{
    __shared__ float sPA[32], sPC[32];
    __shared__ int   sCnt;
    __shared__ float warpT[NW];

    const int bh   = blockIdx.x;
    const int h    = bh % H;
    const int tid  = threadIdx.x;
    const int lane = tid & 31;
    const int warp = tid >> 5;

    const float4* __restrict__ u4 = (const float4*)(u + (size_t)bh * LROW);
    float4* __restrict__       y4 = (float4*)(y + (size_t)bh * LROW);
    const int cbase = warp * CH4 + lane;

    // tiny pole loads first so their latency overlaps the row prefetch
    const int nh = (NH < 32) ? NH : 32;
    float m_ldt = 0.f, m_lA = 0.f, m_C = 0.f;
    if (warp == 0 && lane < nh) {
        m_ldt = log_dt[h];
        m_lA  = log_A_real[h * NH + lane];
        m_C   = C[(h * NH + lane) * 2];
    }

    // prefetch pass-1 data (4 independent LDG.128 per thread, MLP=4)
    float4 f0 = u4[cbase];
    float4 f1 = u4[cbase + 32];
    float4 f2 = u4[cbase + 64];
    float4 f3 = u4[cbase + 96];

    // warp 0: compute poles, merge bitwise-identical ones (convergent)
    if (warp == 0) {
        float dtA, c;
        unsigned mybits;
        if (lane < nh) {
            float dt = expf(m_ldt);
            float A  = -expf(m_lA);
            dtA = A * dt;
            c   = m_C * (expf(dtA) - 1.0f) / A;
            mybits = __float_as_uint(dtA);
        } else {
            dtA = 0.f; c = 0.f;
            mybits = 0xFF800001u ^ (unsigned)lane;   // unique sentinel
        }
        float csum = 0.f;
        int   firstj = 32;
#pragma unroll
        for (int j = 0; j < 32; j++) {
            unsigned bj = __shfl_sync(0xffffffffu, mybits, j);
            float    cj = __shfl_sync(0xffffffffu, c, j);
            if (j < nh && bj == mybits) {
                csum += cj;
                if (j < firstj) firstj = j;
            }
        }
        bool leader = (lane < nh) && (firstj == lane);
        unsigned lb = __ballot_sync(0xffffffffu, leader);
        if (leader) {
            int idx = __popc(lb & ((1u << lane) - 1u));
            sPA[idx] = dtA;
            sPC[idx] = csum;
        }
        if (lane == 0) sCnt = __popc(lb);
    }
    __syncthreads();   // publish poles

    const int cnt = sCnt;

    // pole 0: uses prefetched registers for pass 1, direct store
    do_pole<true, false>(sPA[0], sPC[0], u4, y4, cbase, lane, warp, warpT,
                         f0, f1, f2, f3);

    // remaining poles (generic path; not taken for this dataset): reload +
    // accumulate into y. Barrier protects warpT reuse.
    for (int p = 1; p < cnt; p++) {
        __syncthreads();
        do_pole<false, true>(sPA[p], sPC[p], u4, y4, cbase, lane, warp, warpT,
                             f0, f1, f2, f3);
    }
}

// ---------------------------------------------------------------------------
extern "C" void kernel_launch(void* const* d_in, const int* in_sizes, int n_in,
                              void* d_out, int out_size) {
    const float* u          = (const float*)d_in[0];   // (B,H,L)
    const float* C          = (const float*)d_in[1];   // (H,N/2,2)
    const float* log_dt     = (const float*)d_in[2];   // (H,)
    const float* log_A_real = (const float*)d_in[3];   // (H,N/2)
    float*       y          = (float*)d_out;

    const int H    = in_sizes[2];
    const int NH   = in_sizes[3] / H;
    const int rows = in_sizes[0] / LROW;               // B*H

    s4d_fused<<<rows, TPB>>>(u, C, log_dt, log_A_real, y, H, NH);
}